// round 2
// baseline (speedup 1.0000x reference)
#include <cuda_runtime.h>
#include <math.h>

// Problem constants
#define BATCH 4096
#define DIM   64

// Tiling: 2 rows per warp, 4 warps per block -> 8 rows/block, 512 blocks, 2048 warps
#define R     2
#define WPB   4
#define THREADS (WPB * 32)
#define ROWS_PER_BLOCK (R * WPB)                 // 8
#define NBLOCKS (BATCH / ROWS_PER_BLOCK)         // 512

#define MAX_IT 100
#define DTOL   5e-5f

// W shared layout: 32 lane-rows, pitch 132 floats (33 x 16B).
// Lane l's row holds, for j=0..63, the packed pair (W[l][j], W[l+32][j]).
// Group jc (16B) = { W[l][2jc], W[l+32][2jc], W[l][2jc+1], W[l+32][2jc+1] }.
// LDS.128 at word addr 132*l + 4*jc: 132 mod 32 = 4 -> per 8-lane phase the
// 4-word ranges start at distinct 4*l offsets -> conflict-free.
#define WPITCH_F 132

typedef unsigned long long u64;

__device__ __forceinline__ u64 pk(float lo, float hi) {
    u64 r; asm("mov.b64 %0, {%1, %2};" : "=l"(r) : "f"(lo), "f"(hi)); return r;
}
__device__ __forceinline__ void upk(float& lo, float& hi, u64 v) {
    asm("mov.b64 {%0, %1}, %2;" : "=f"(lo), "=f"(hi) : "l"(v));
}
// Packed dual-FMA: d.lo += a.lo*b.lo ; d.hi += a.hi*b.hi  (one FMA-pipe instr)
__device__ __forceinline__ void fma2(u64& d, u64 a, u64 b) {
    asm("fma.rn.f32x2 %0, %1, %2, %0;" : "+l"(d) : "l"(a), "l"(b));
}

// Accurate tanh independent of --use_fast_math lowering of tanhf.
__device__ __forceinline__ float my_tanh(float a) {
    float aa = fabsf(a);
    float e  = __expf(-2.0f * aa);          // MUFU.EX2 path, ~2^-21 rel err
    float t  = (1.0f - e) / (1.0f + e);
    return copysignf(t, a);
}

__global__ void __launch_bounds__(THREADS)
tanh_fixed_point_kernel(const float* __restrict__ x,
                        const float* __restrict__ W,
                        float* __restrict__ out)
{
    __shared__ __align__(16) float Wsh[32 * WPITCH_F];
    // Ping-pong duplicated-z buffers: zd[p][warp][r][2*DIM] with zd[..][2j]=zd[..][2j+1]=z_j
    __shared__ __align__(16) float zd[2][WPB][R][2 * DIM];

    const int tid  = threadIdx.x;
    const int lane = tid & 31;
    const int warp = tid >> 5;

    // Stage W into packed-pair layout
    for (int idx = tid; idx < DIM * DIM; idx += THREADS) {
        int i = idx >> 6;
        int j = idx & 63;
        Wsh[(i & 31) * WPITCH_F + ((j >> 1) << 2) + ((j & 1) << 1) + (i >> 5)] = W[idx];
    }
    __syncthreads();

    const int row0 = blockIdx.x * ROWS_PER_BLOCK + warp * R;

    // Per-lane state: components i=lane (lo) and i=lane+32 (hi) of each row
    float z0[R], z1[R];
    u64   xr2[R];
    #pragma unroll
    for (int r = 0; r < R; r++) {
        float x0 = x[(row0 + r) * DIM + lane];
        float x1 = x[(row0 + r) * DIM + lane + 32];
        xr2[r] = pk(x0, x1);
        z0[r] = my_tanh(x0);
        z1[r] = my_tanh(x1);
        float2* zrow = (float2*)zd[0][warp][r];
        zrow[lane]      = make_float2(z0[r], z0[r]);
        zrow[lane + 32] = make_float2(z1[r], z1[r]);
    }
    __syncwarp();

    const ulonglong2* Wp = ((const ulonglong2*)Wsh) + lane * (WPITCH_F / 4);

    int p = 0;
    for (int it = 0; it < MAX_IT; it++) {
        u64 accA[R], accB[R];
        #pragma unroll
        for (int r = 0; r < R; r++) { accA[r] = xr2[r]; accB[r] = pk(0.0f, 0.0f); }

        const ulonglong2* Zp[R];
        #pragma unroll
        for (int r = 0; r < R; r++) Zp[r] = (const ulonglong2*)zd[p][warp][r];

        // zl_i = x_i + sum_j W[i][j] z_j ; packed over (i, i+32), 4 indep chains
        #pragma unroll
        for (int jc = 0; jc < 16; jc++) {
            ulonglong2 wa = Wp[jc];        // pairs for j = 2jc, 2jc+1
            ulonglong2 wb = Wp[jc + 16];   // pairs for j = 2jc+32, 2jc+33
            #pragma unroll
            for (int r = 0; r < R; r++) {
                ulonglong2 za = Zp[r][jc];       // (z_j,z_j),(z_j+1,z_j+1) broadcast
                ulonglong2 zb = Zp[r][jc + 16];
                fma2(accA[r], wa.x, za.x);
                fma2(accA[r], wa.y, za.y);
                fma2(accB[r], wb.x, zb.x);
                fma2(accB[r], wb.y, zb.y);
            }
        }

        bool conv = true;
        #pragma unroll
        for (int r = 0; r < R; r++) {
            float a0, a1, b0, b1;
            upk(a0, a1, accA[r]);
            upk(b0, b1, accB[r]);
            float n0 = my_tanh(a0 + b0);
            float n1 = my_tanh(a1 + b1);
            conv = conv && (fabsf(n0 - z0[r]) < DTOL) && (fabsf(n1 - z1[r]) < DTOL);
            z0[r] = n0; z1[r] = n1;
            float2* zrow = (float2*)zd[p ^ 1][warp][r];
            zrow[lane]      = make_float2(n0, n0);
            zrow[lane + 32] = make_float2(n1, n1);
        }
        p ^= 1;
        __syncwarp();                       // stores visible before next iter's loads
        if (__all_sync(0xffffffffu, conv)) break;
    }

    #pragma unroll
    for (int r = 0; r < R; r++) {
        out[(row0 + r) * DIM + lane]      = z0[r];
        out[(row0 + r) * DIM + lane + 32] = z1[r];
    }
}

extern "C" void kernel_launch(void* const* d_in, const int* in_sizes, int n_in,
                              void* d_out, int out_size)
{
    const float* x = (const float*)d_in[0];   // [4096, 64]
    const float* W = (const float*)d_in[1];   // [64, 64]
    float* out = (float*)d_out;               // [4096, 64]
    (void)in_sizes; (void)n_in; (void)out_size;

    tanh_fixed_point_kernel<<<NBLOCKS, THREADS>>>(x, W, out);
}

// round 3
// speedup vs baseline: 1.8458x; 1.8458x over previous
#include <cuda_runtime.h>
#include <math.h>

// Problem constants
#define BATCH 4096
#define DIM   64

// Tiling: 4 rows per warp, 4 warps per block -> 16 rows/block, 256 blocks, 1024 warps
#define R     4
#define WPB   4
#define THREADS (WPB * 32)
#define ROWS_PER_BLOCK (R * WPB)                 // 16
#define NBLOCKS (BATCH / ROWS_PER_BLOCK)         // 256

#define MAX_IT 100
#define DTOL   1.5e-4f

#define WPITCH 68   // one-time staging pitch

typedef unsigned long long u64;

__device__ __forceinline__ u64 pk(float lo, float hi) {
    u64 r; asm("mov.b64 %0, {%1, %2};" : "=l"(r) : "f"(lo), "f"(hi)); return r;
}
__device__ __forceinline__ void upk(float& lo, float& hi, u64 v) {
    asm("mov.b64 {%0, %1}, %2;" : "=f"(lo), "=f"(hi) : "l"(v));
}
// Packed dual-FMA on the FMA pipe: d.lo += a.lo*b.lo ; d.hi += a.hi*b.hi
__device__ __forceinline__ void fma2(u64& d, u64 a, u64 b) {
    asm("fma.rn.f32x2 %0, %1, %2, %0;" : "+l"(d) : "l"(a), "l"(b));
}

// Accurate tanh (~1e-6 abs err), cheap: MUFU.EX2 + MUFU.RCP path.
__device__ __forceinline__ float my_tanh(float a) {
    float aa = fabsf(a);
    float e  = __expf(-2.0f * aa);                 // in (0, 1]
    float t  = __fdividef(1.0f - e, 1.0f + e);     // |tanh|, denom in [1,2]: safe
    return copysignf(t, a);
}

__global__ void __launch_bounds__(THREADS)
tanh_fixed_point_kernel(const float* __restrict__ x,
                        const float* __restrict__ W,
                        float* __restrict__ out)
{
    __shared__ __align__(16) float Wsh[DIM * WPITCH];      // one-time stage
    __shared__ __align__(16) float zsh[WPB][R][DIM];       // current z per warp-row

    const int tid  = threadIdx.x;
    const int lane = tid & 31;
    const int warp = tid >> 5;

    // One-time coalesced stage of W into shared
    for (int idx = tid; idx < DIM * DIM; idx += THREADS) {
        int i = idx >> 6;
        int j = idx & 63;
        Wsh[i * WPITCH + j] = W[idx];
    }
    __syncthreads();

    // W -> registers, packed over consecutive j:
    //   wA[jc] = (W[lane][2jc],   W[lane][2jc+1])
    //   wB[jc] = (W[lane+32][2jc],W[lane+32][2jc+1])
    u64 wA[32], wB[32];
    {
        const u64* rowA = reinterpret_cast<const u64*>(&Wsh[lane * WPITCH]);
        const u64* rowB = reinterpret_cast<const u64*>(&Wsh[(lane + 32) * WPITCH]);
        #pragma unroll
        for (int jc = 0; jc < 32; jc++) { wA[jc] = rowA[jc]; wB[jc] = rowB[jc]; }
    }

    const int row0 = blockIdx.x * ROWS_PER_BLOCK + warp * R;

    // Per-lane state: components i=lane ([0]) and i=lane+32 ([1]) of each row
    float xr[R][2], z[R][2];
    #pragma unroll
    for (int r = 0; r < R; r++) {
        xr[r][0] = x[(row0 + r) * DIM + lane];
        xr[r][1] = x[(row0 + r) * DIM + lane + 32];
        z[r][0]  = my_tanh(xr[r][0]);
        z[r][1]  = my_tanh(xr[r][1]);
    }

    for (int it = 0; it < MAX_IT; it++) {
        // Stage current z (non-duplicated)
        #pragma unroll
        for (int r = 0; r < R; r++) {
            zsh[warp][r][lane]      = z[r][0];
            zsh[warp][r][lane + 32] = z[r][1];
        }
        __syncwarp();

        // acc[r][k]: packed (even-j partial, odd-j partial); x folded into lo
        u64 acc[R][2];
        #pragma unroll
        for (int r = 0; r < R; r++) {
            acc[r][0] = pk(xr[r][0], 0.0f);
            acc[r][1] = pk(xr[r][1], 0.0f);
        }

        // zl_i = x_i + sum_j W[i][j] z_j, j-pair packed; W from registers,
        // z pairs direct from LDS.128 broadcasts (no packing needed).
        #pragma unroll
        for (int jq = 0; jq < 16; jq++) {
            #pragma unroll
            for (int r = 0; r < R; r++) {
                ulonglong2 zp = reinterpret_cast<const ulonglong2*>(zsh[warp][r])[jq];
                fma2(acc[r][0], wA[2 * jq],     zp.x);
                fma2(acc[r][0], wA[2 * jq + 1], zp.y);
                fma2(acc[r][1], wB[2 * jq],     zp.x);
                fma2(acc[r][1], wB[2 * jq + 1], zp.y);
            }
        }

        // Horizontal combine + tanh + convergence
        bool conv = true;
        #pragma unroll
        for (int r = 0; r < R; r++) {
            #pragma unroll
            for (int k = 0; k < 2; k++) {
                float lo, hi;
                upk(lo, hi, acc[r][k]);
                float n = my_tanh(lo + hi);
                conv = conv && (fabsf(n - z[r][k]) < DTOL);
                z[r][k] = n;
            }
        }

        __syncwarp();   // all lanes done reading zsh before next store
        if (__all_sync(0xffffffffu, conv)) break;
    }

    #pragma unroll
    for (int r = 0; r < R; r++) {
        out[(row0 + r) * DIM + lane]      = z[r][0];
        out[(row0 + r) * DIM + lane + 32] = z[r][1];
    }
}

extern "C" void kernel_launch(void* const* d_in, const int* in_sizes, int n_in,
                              void* d_out, int out_size)
{
    const float* x = (const float*)d_in[0];   // [4096, 64]
    const float* W = (const float*)d_in[1];   // [64, 64]
    float* out = (float*)d_out;               // [4096, 64]
    (void)in_sizes; (void)n_in; (void)out_size;

    tanh_fixed_point_kernel<<<NBLOCKS, THREADS>>>(x, W, out);
}